// round 15
// baseline (speedup 1.0000x reference)
#include <cuda_runtime.h>
#include <math.h>
#include <stdint.h>

#define B_ 64
#define T_ 1024
#define H_ 256
#define M_ (B_*T_)   /* 65536 rows for the projection GEMMs */

// Scratch (device globals — no runtime allocation allowed)
__device__ float g_xp[B_*T_*H_];   // input-projection result for current layer
__device__ float g_h [B_*T_*H_];   // layer-0 hidden sequence
// Exchange slots: [batch][dest_rank][buf][jl] tagged 8B words (val, tag).
// Zeroed via cudaMemsetAsync before each scan launch (kills stale tags
// across graph replays).
__device__ unsigned long long g_slots[B_][2][2][128];

// ---------------------------------------------------------------------------
// packed f32x2 helpers (sm_100+): one instr = 2 fp32 FMAs
// ---------------------------------------------------------------------------
__device__ __forceinline__ unsigned long long ffma2(unsigned long long a,
                                                    unsigned long long b,
                                                    unsigned long long c) {
    unsigned long long d;
    asm("fma.rn.f32x2 %0, %1, %2, %3;" : "=l"(d) : "l"(a), "l"(b), "l"(c));
    return d;
}
__device__ __forceinline__ unsigned long long pack2(float lo, float hi) {
    unsigned long long r;
    asm("mov.b64 %0, {%1, %2};"
        : "=l"(r) : "r"(__float_as_uint(lo)), "r"(__float_as_uint(hi)));
    return r;
}
__device__ __forceinline__ float2 unpack2(unsigned long long v) {
    uint32_t lo, hi;
    asm("mov.b64 {%0, %1}, %2;" : "=r"(lo), "=r"(hi) : "l"(v));
    return make_float2(__uint_as_float(lo), __uint_as_float(hi));
}
// Fast accurate-enough tanh: ~1e-7 rel err, MUFU-based (no branches).
__device__ __forceinline__ float tanh_fast(float x) {
    float xc = fminf(fmaxf(x, -9.0f), 9.0f);     // tanh(9)=1-3e-8
    float e  = __expf(2.0f * xc);
    return __fdividef(e - 1.0f, e + 1.0f);
}

// ---------------------------------------------------------------------------
// Projection GEMM: out[M,256] = A[M,256] @ W[256,256]^T + bias
// (unchanged: near the fp32 FFMA2 ceiling)
// ---------------------------------------------------------------------------
__global__ void __launch_bounds__(256, 2)
gemm_bias(const float* __restrict__ A, const float* __restrict__ W,
          const float* __restrict__ bias, float* __restrict__ out)
{
    __shared__ __align__(16) float As[16][128];
    __shared__ __align__(16) float Bs[16][64];

    const int tid = threadIdx.x;
    const int m0  = blockIdx.x * 128;
    const int n0  = blockIdx.y * 64;
    const int tx  = tid & 15;
    const int ty  = tid >> 4;
    const int lm  = tid >> 1;
    const int ak  = (tid & 1) * 8;
    const int ln  = tid & 63;
    const int bk  = (tid >> 6) * 4;

    unsigned long long acc[4][4];
#pragma unroll
    for (int p = 0; p < 4; p++)
#pragma unroll
        for (int n = 0; n < 4; n++) acc[p][n] = 0ull;

    const float* Arow = A + (size_t)(m0 + lm) * H_;
    const float* Wrow = W + (size_t)(n0 + ln) * H_;

    for (int k0 = 0; k0 < H_; k0 += 16) {
        float4 av0 = *(const float4*)(Arow + k0 + ak);
        float4 av1 = *(const float4*)(Arow + k0 + ak + 4);
        float4 bv0 = *(const float4*)(Wrow + k0 + bk);
        As[ak+0][lm] = av0.x; As[ak+1][lm] = av0.y;
        As[ak+2][lm] = av0.z; As[ak+3][lm] = av0.w;
        As[ak+4][lm] = av1.x; As[ak+5][lm] = av1.y;
        As[ak+6][lm] = av1.z; As[ak+7][lm] = av1.w;
        Bs[bk+0][ln] = bv0.x; Bs[bk+1][ln] = bv0.y;
        Bs[bk+2][ln] = bv0.z; Bs[bk+3][ln] = bv0.w;
        __syncthreads();
#pragma unroll
        for (int k = 0; k < 16; k++) {
            const ulonglong2* ap = (const ulonglong2*)&As[k][ty * 8];
            ulonglong2 q0 = ap[0];
            ulonglong2 q1 = ap[1];
            float4 bv = *(const float4*)&Bs[k][tx * 4];
            unsigned long long b0 = pack2(bv.x, bv.x);
            unsigned long long b1 = pack2(bv.y, bv.y);
            unsigned long long b2 = pack2(bv.z, bv.z);
            unsigned long long b3 = pack2(bv.w, bv.w);
            acc[0][0]=ffma2(q0.x,b0,acc[0][0]); acc[0][1]=ffma2(q0.x,b1,acc[0][1]);
            acc[0][2]=ffma2(q0.x,b2,acc[0][2]); acc[0][3]=ffma2(q0.x,b3,acc[0][3]);
            acc[1][0]=ffma2(q0.y,b0,acc[1][0]); acc[1][1]=ffma2(q0.y,b1,acc[1][1]);
            acc[1][2]=ffma2(q0.y,b2,acc[1][2]); acc[1][3]=ffma2(q0.y,b3,acc[1][3]);
            acc[2][0]=ffma2(q1.x,b0,acc[2][0]); acc[2][1]=ffma2(q1.x,b1,acc[2][1]);
            acc[2][2]=ffma2(q1.x,b2,acc[2][2]); acc[2][3]=ffma2(q1.x,b3,acc[2][3]);
            acc[3][0]=ffma2(q1.y,b0,acc[3][0]); acc[3][1]=ffma2(q1.y,b1,acc[3][1]);
            acc[3][2]=ffma2(q1.y,b2,acc[3][2]); acc[3][3]=ffma2(q1.y,b3,acc[3][3]);
        }
        __syncthreads();
    }

    float4 bb = *(const float4*)(bias + n0 + tx * 4);
#pragma unroll
    for (int p = 0; p < 4; p++) {
        float2 c0 = unpack2(acc[p][0]);
        float2 c1 = unpack2(acc[p][1]);
        float2 c2 = unpack2(acc[p][2]);
        float2 c3 = unpack2(acc[p][3]);
        float4 lo = make_float4(c0.x + bb.x, c1.x + bb.y, c2.x + bb.z, c3.x + bb.w);
        float4 hi = make_float4(c0.y + bb.x, c1.y + bb.y, c2.y + bb.z, c3.y + bb.w);
        size_t r = (size_t)(m0 + ty * 8 + 2 * p) * H_ + n0 + tx * 4;
        *(float4*)(out + r)      = lo;
        *(float4*)(out + r + H_) = hi;
    }
}

// ---------------------------------------------------------------------------
// Recurrent scan, round 15: L2 exchange (NO cluster, NO DSMEM).
//  Flight-hypothesis test: rounds 6-13 plateau at step~1500 regardless of
//  handshake primitive => the DSMEM store->remote-visibility (~1000cyc @NAT)
//  is the dominant term. Replace it with L2: plain CTA pairs (2b, 2b+1),
//  senders st.volatile.global.b64 a tagged (partial, tag=t+1) word (aligned
//  8B = single-copy atomic, flag IS the data word); receivers spin on
//  ld.volatile.global.b64 until tag matches. One-way ~600-750cyc @NAT.
//  - grid=128 = one wave on 148 SMs -> pair co-residency guaranteed (no
//    deadlock; no cluster scheduling needed).
//  - slots zeroed by cudaMemsetAsync before each scan launch (stale-tag
//    kill across graph replays).
//  - slot WAR (reuse at t+2) ordered by the message chain + per-step bar:
//    sender's t+2 write <- its CTA's h[t+2] <- peer partial t+1 <- peer
//    sent after its bar(t) <- peer receiver's slot read at t.
//  - everything else = round-13 skeleton (8-chain dot, tanh_fast, local
//    hs + one __syncthreads per step, xp prefetch).
// ---------------------------------------------------------------------------
__global__ void __launch_bounds__(256, 1)
elman_scan(const float* __restrict__ xp, const float* __restrict__ Whh,
           float* __restrict__ ys, unsigned long long* __restrict__ slots)
{
    __shared__ __align__(16) float hs[2][128];     // local h half, double-buf

    const int tid  = threadIdx.x;
    const int rank = (int)(blockIdx.x & 1);
    const int batch= (int)(blockIdx.x >> 1);
    const int j    = tid;              // global output index owned by thread
    const int jl   = tid & 127;        // index within its half
    const bool mine = ((tid >> 7) == rank);   // my-half warps (4 of 8)

    // Weights: W_hh[j][rank*128 .. +127] as 64 packed f32x2 (local k-half)
    unsigned long long w[64];
    {
        const ulonglong2* wv =
            (const ulonglong2*)(Whh + (size_t)j * H_ + rank * 128);
#pragma unroll
        for (int i = 0; i < 32; i++) {
            ulonglong2 v = wv[i];
            w[2*i] = v.x; w[2*i+1] = v.y;
        }
    }

    if (tid < 128) { hs[0][tid] = 0.0f; hs[1][tid] = 0.0f; }
    __syncthreads();

    // Slot addresses: [batch][dest_rank][buf][jl]
    unsigned long long* send_base =
        slots + (((size_t)batch * 2 + (size_t)(rank ^ 1)) * 2) * 128 + jl;
    unsigned long long* recv_base =
        slots + (((size_t)batch * 2 + (size_t)rank) * 2) * 128 + jl;

    const float* xpb = xp + (size_t)batch * T_ * H_;
    float*       ysb = ys + (size_t)batch * T_ * H_;

    float x_cur = 0.0f, x_next = 0.0f;
    if (mine) x_cur = __ldg(xpb + j);      // xp[t=0][j]

    for (int t = 0; t < T_; t++) {
        const uint32_t buf = (uint32_t)(t & 1);
        // --- local-k partial: 8 chains of 8 FFMA2 (depth 32cyc) -----------
        const ulonglong2* hv = (const ulonglong2*)&hs[buf][0];
        unsigned long long a0=0ull,a1=0ull,a2=0ull,a3=0ull,
                           a4=0ull,a5=0ull,a6=0ull,a7=0ull;
#pragma unroll
        for (int i = 0; i < 8; i++) {
            ulonglong2 p = hv[4*i];
            ulonglong2 q = hv[4*i + 1];
            ulonglong2 r = hv[4*i + 2];
            ulonglong2 u = hv[4*i + 3];
            a0 = ffma2(w[8*i+0], p.x, a0);
            a1 = ffma2(w[8*i+1], p.y, a1);
            a2 = ffma2(w[8*i+2], q.x, a2);
            a3 = ffma2(w[8*i+3], q.y, a3);
            a4 = ffma2(w[8*i+4], r.x, a4);
            a5 = ffma2(w[8*i+5], r.y, a5);
            a6 = ffma2(w[8*i+6], u.x, a6);
            a7 = ffma2(w[8*i+7], u.y, a7);
        }
        float2 f0=unpack2(a0), f1=unpack2(a1), f2=unpack2(a2), f3=unpack2(a3);
        float2 f4=unpack2(a4), f5=unpack2(a5), f6=unpack2(a6), f7=unpack2(a7);
        float s = (((f0.x+f0.y)+(f1.x+f1.y)) + ((f2.x+f2.y)+(f3.x+f3.y))) +
                  (((f4.x+f4.y)+(f5.x+f5.y)) + ((f6.x+f6.y)+(f7.x+f7.y)));

        if (!mine) {
            // Publish (partial, tag=t+1) through L2. Single-copy atomic 8B.
            unsigned long long msg;
            asm("mov.b64 %0, {%1, %2};"
                : "=l"(msg)
                : "r"(__float_as_uint(s)), "r"((uint32_t)(t + 1)));
            asm volatile("st.volatile.global.b64 [%0], %1;"
                         :: "l"(send_base + (size_t)buf * 128), "l"(msg)
                         : "memory");
        } else {
            if (t + 1 < T_)
                x_next = __ldg(xpb + (size_t)(t + 1) * H_ + j);
            // Spin on L2 until this step's tag shows up (value rides along).
            const unsigned long long* addr = recv_base + (size_t)buf * 128;
            const uint32_t want = (uint32_t)(t + 1);
            uint32_t lo, hi;
            do {
                asm volatile("ld.volatile.global.v2.u32 {%0, %1}, [%2];"
                             : "=r"(lo), "=r"(hi) : "l"(addr) : "memory");
            } while (hi != want);
            float v = tanh_fast(s + __uint_as_float(lo) + x_cur);
            ysb[(size_t)t * H_ + j] = v;
            if (t + 1 < T_) hs[buf ^ 1u][jl] = v;
            x_cur = x_next;
        }
        __syncthreads();   // h[t+1] visible to senders; local WAR fence
    }
}

// ---------------------------------------------------------------------------
// Launch: gemm0 -> memset -> scan0 -> gemm1 -> memset -> scan1
// ---------------------------------------------------------------------------
extern "C" void kernel_launch(void* const* d_in, const int* in_sizes, int n_in,
                              void* d_out, int out_size)
{
    const float* x     = (const float*)d_in[0];
    const float* W_ih0 = (const float*)d_in[1];
    const float* b_ih0 = (const float*)d_in[2];
    const float* W_hh0 = (const float*)d_in[3];
    const float* W_ih1 = (const float*)d_in[4];
    const float* b_ih1 = (const float*)d_in[5];
    const float* W_hh1 = (const float*)d_in[6];
    float* out = (float*)d_out;

    float *xp, *h;
    unsigned long long* slots;
    cudaGetSymbolAddress((void**)&xp, g_xp);
    cudaGetSymbolAddress((void**)&h,  g_h);
    cudaGetSymbolAddress((void**)&slots, g_slots);
    const size_t slot_bytes = (size_t)B_ * 2 * 2 * 128 * 8;

    dim3 ggrid(M_ / 128, H_ / 64);   // (512, 4)

    gemm_bias<<<ggrid, 256>>>(x, W_ih0, b_ih0, xp);
    cudaMemsetAsync(slots, 0, slot_bytes);
    elman_scan<<<B_ * 2, 256>>>(xp, W_hh0, h, slots);
    gemm_bias<<<ggrid, 256>>>(h, W_ih1, b_ih1, xp);
    cudaMemsetAsync(slots, 0, slot_bytes);
    elman_scan<<<B_ * 2, 256>>>(xp, W_hh1, out, slots);
}

// round 16
// speedup vs baseline: 1.0117x; 1.0117x over previous
#include <cuda_runtime.h>
#include <math.h>
#include <stdint.h>

#define B_ 64
#define T_ 1024
#define H_ 256
#define M_ (B_*T_)   /* 65536 rows for the projection GEMMs */

// Scratch (device globals — no runtime allocation allowed)
__device__ float g_xp[B_*T_*H_];   // input-projection result for current layer
__device__ float g_h [B_*T_*H_];   // layer-0 hidden sequence
// Exchange slots: [batch][dest_rank][buf][jl] tagged 8B words (val, tag).
// Zeroed via cudaMemsetAsync before each scan launch (kills stale tags
// across graph replays).
__device__ unsigned long long g_slots[B_][2][2][128];

// ---------------------------------------------------------------------------
// packed f32x2 helpers (sm_100+): one instr = 2 fp32 FMAs
// ---------------------------------------------------------------------------
__device__ __forceinline__ unsigned long long ffma2(unsigned long long a,
                                                    unsigned long long b,
                                                    unsigned long long c) {
    unsigned long long d;
    asm("fma.rn.f32x2 %0, %1, %2, %3;" : "=l"(d) : "l"(a), "l"(b), "l"(c));
    return d;
}
__device__ __forceinline__ unsigned long long pack2(float lo, float hi) {
    unsigned long long r;
    asm("mov.b64 %0, {%1, %2};"
        : "=l"(r) : "r"(__float_as_uint(lo)), "r"(__float_as_uint(hi)));
    return r;
}
__device__ __forceinline__ float2 unpack2(unsigned long long v) {
    uint32_t lo, hi;
    asm("mov.b64 {%0, %1}, %2;" : "=r"(lo), "=r"(hi) : "l"(v));
    return make_float2(__uint_as_float(lo), __uint_as_float(hi));
}
// Fast accurate-enough tanh: ~1e-7 rel err, MUFU-based (no branches).
__device__ __forceinline__ float tanh_fast(float x) {
    float xc = fminf(fmaxf(x, -9.0f), 9.0f);     // tanh(9)=1-3e-8
    float e  = __expf(2.0f * xc);
    return __fdividef(e - 1.0f, e + 1.0f);
}

// ---------------------------------------------------------------------------
// Projection GEMM: out[M,256] = A[M,256] @ W[256,256]^T + bias
// (unchanged: near the fp32 FFMA2 ceiling)
// ---------------------------------------------------------------------------
__global__ void __launch_bounds__(256, 2)
gemm_bias(const float* __restrict__ A, const float* __restrict__ W,
          const float* __restrict__ bias, float* __restrict__ out)
{
    __shared__ __align__(16) float As[16][128];
    __shared__ __align__(16) float Bs[16][64];

    const int tid = threadIdx.x;
    const int m0  = blockIdx.x * 128;
    const int n0  = blockIdx.y * 64;
    const int tx  = tid & 15;
    const int ty  = tid >> 4;
    const int lm  = tid >> 1;
    const int ak  = (tid & 1) * 8;
    const int ln  = tid & 63;
    const int bk  = (tid >> 6) * 4;

    unsigned long long acc[4][4];
#pragma unroll
    for (int p = 0; p < 4; p++)
#pragma unroll
        for (int n = 0; n < 4; n++) acc[p][n] = 0ull;

    const float* Arow = A + (size_t)(m0 + lm) * H_;
    const float* Wrow = W + (size_t)(n0 + ln) * H_;

    for (int k0 = 0; k0 < H_; k0 += 16) {
        float4 av0 = *(const float4*)(Arow + k0 + ak);
        float4 av1 = *(const float4*)(Arow + k0 + ak + 4);
        float4 bv0 = *(const float4*)(Wrow + k0 + bk);
        As[ak+0][lm] = av0.x; As[ak+1][lm] = av0.y;
        As[ak+2][lm] = av0.z; As[ak+3][lm] = av0.w;
        As[ak+4][lm] = av1.x; As[ak+5][lm] = av1.y;
        As[ak+6][lm] = av1.z; As[ak+7][lm] = av1.w;
        Bs[bk+0][ln] = bv0.x; Bs[bk+1][ln] = bv0.y;
        Bs[bk+2][ln] = bv0.z; Bs[bk+3][ln] = bv0.w;
        __syncthreads();
#pragma unroll
        for (int k = 0; k < 16; k++) {
            const ulonglong2* ap = (const ulonglong2*)&As[k][ty * 8];
            ulonglong2 q0 = ap[0];
            ulonglong2 q1 = ap[1];
            float4 bv = *(const float4*)&Bs[k][tx * 4];
            unsigned long long b0 = pack2(bv.x, bv.x);
            unsigned long long b1 = pack2(bv.y, bv.y);
            unsigned long long b2 = pack2(bv.z, bv.z);
            unsigned long long b3 = pack2(bv.w, bv.w);
            acc[0][0]=ffma2(q0.x,b0,acc[0][0]); acc[0][1]=ffma2(q0.x,b1,acc[0][1]);
            acc[0][2]=ffma2(q0.x,b2,acc[0][2]); acc[0][3]=ffma2(q0.x,b3,acc[0][3]);
            acc[1][0]=ffma2(q0.y,b0,acc[1][0]); acc[1][1]=ffma2(q0.y,b1,acc[1][1]);
            acc[1][2]=ffma2(q0.y,b2,acc[1][2]); acc[1][3]=ffma2(q0.y,b3,acc[1][3]);
            acc[2][0]=ffma2(q1.x,b0,acc[2][0]); acc[2][1]=ffma2(q1.x,b1,acc[2][1]);
            acc[2][2]=ffma2(q1.x,b2,acc[2][2]); acc[2][3]=ffma2(q1.x,b3,acc[2][3]);
            acc[3][0]=ffma2(q1.y,b0,acc[3][0]); acc[3][1]=ffma2(q1.y,b1,acc[3][1]);
            acc[3][2]=ffma2(q1.y,b2,acc[3][2]); acc[3][3]=ffma2(q1.y,b3,acc[3][3]);
        }
        __syncthreads();
    }

    float4 bb = *(const float4*)(bias + n0 + tx * 4);
#pragma unroll
    for (int p = 0; p < 4; p++) {
        float2 c0 = unpack2(acc[p][0]);
        float2 c1 = unpack2(acc[p][1]);
        float2 c2 = unpack2(acc[p][2]);
        float2 c3 = unpack2(acc[p][3]);
        float4 lo = make_float4(c0.x + bb.x, c1.x + bb.y, c2.x + bb.z, c3.x + bb.w);
        float4 hi = make_float4(c0.y + bb.x, c1.y + bb.y, c2.y + bb.z, c3.y + bb.w);
        size_t r = (size_t)(m0 + ty * 8 + 2 * p) * H_ + n0 + tx * 4;
        *(float4*)(out + r)      = lo;
        *(float4*)(out + r + H_) = hi;
    }
}

// ---------------------------------------------------------------------------
// Recurrent scan, round 15: L2 exchange (NO cluster, NO DSMEM).
//  Flight-hypothesis test: rounds 6-13 plateau at step~1500 regardless of
//  handshake primitive => the DSMEM store->remote-visibility (~1000cyc @NAT)
//  is the dominant term. Replace it with L2: plain CTA pairs (2b, 2b+1),
//  senders st.volatile.global.b64 a tagged (partial, tag=t+1) word (aligned
//  8B = single-copy atomic, flag IS the data word); receivers spin on
//  ld.volatile.global.b64 until tag matches. One-way ~600-750cyc @NAT.
//  - grid=128 = one wave on 148 SMs -> pair co-residency guaranteed (no
//    deadlock; no cluster scheduling needed).
//  - slots zeroed by cudaMemsetAsync before each scan launch (stale-tag
//    kill across graph replays).
//  - slot WAR (reuse at t+2) ordered by the message chain + per-step bar:
//    sender's t+2 write <- its CTA's h[t+2] <- peer partial t+1 <- peer
//    sent after its bar(t) <- peer receiver's slot read at t.
//  - everything else = round-13 skeleton (8-chain dot, tanh_fast, local
//    hs + one __syncthreads per step, xp prefetch).
// ---------------------------------------------------------------------------
__global__ void __launch_bounds__(256, 1)
elman_scan(const float* __restrict__ xp, const float* __restrict__ Whh,
           float* __restrict__ ys, unsigned long long* __restrict__ slots)
{
    __shared__ __align__(16) float hs[2][128];     // local h half, double-buf

    const int tid  = threadIdx.x;
    const int rank = (int)(blockIdx.x & 1);
    const int batch= (int)(blockIdx.x >> 1);
    const int j    = tid;              // global output index owned by thread
    const int jl   = tid & 127;        // index within its half
    const bool mine = ((tid >> 7) == rank);   // my-half warps (4 of 8)

    // Weights: W_hh[j][rank*128 .. +127] as 64 packed f32x2 (local k-half)
    unsigned long long w[64];
    {
        const ulonglong2* wv =
            (const ulonglong2*)(Whh + (size_t)j * H_ + rank * 128);
#pragma unroll
        for (int i = 0; i < 32; i++) {
            ulonglong2 v = wv[i];
            w[2*i] = v.x; w[2*i+1] = v.y;
        }
    }

    if (tid < 128) { hs[0][tid] = 0.0f; hs[1][tid] = 0.0f; }
    __syncthreads();

    // Slot addresses: [batch][dest_rank][buf][jl]
    unsigned long long* send_base =
        slots + (((size_t)batch * 2 + (size_t)(rank ^ 1)) * 2) * 128 + jl;
    unsigned long long* recv_base =
        slots + (((size_t)batch * 2 + (size_t)rank) * 2) * 128 + jl;

    const float* xpb = xp + (size_t)batch * T_ * H_;
    float*       ysb = ys + (size_t)batch * T_ * H_;

    float x_cur = 0.0f, x_next = 0.0f;
    if (mine) x_cur = __ldg(xpb + j);      // xp[t=0][j]

    for (int t = 0; t < T_; t++) {
        const uint32_t buf = (uint32_t)(t & 1);
        // --- local-k partial: 8 chains of 8 FFMA2 (depth 32cyc) -----------
        const ulonglong2* hv = (const ulonglong2*)&hs[buf][0];
        unsigned long long a0=0ull,a1=0ull,a2=0ull,a3=0ull,
                           a4=0ull,a5=0ull,a6=0ull,a7=0ull;
#pragma unroll
        for (int i = 0; i < 8; i++) {
            ulonglong2 p = hv[4*i];
            ulonglong2 q = hv[4*i + 1];
            ulonglong2 r = hv[4*i + 2];
            ulonglong2 u = hv[4*i + 3];
            a0 = ffma2(w[8*i+0], p.x, a0);
            a1 = ffma2(w[8*i+1], p.y, a1);
            a2 = ffma2(w[8*i+2], q.x, a2);
            a3 = ffma2(w[8*i+3], q.y, a3);
            a4 = ffma2(w[8*i+4], r.x, a4);
            a5 = ffma2(w[8*i+5], r.y, a5);
            a6 = ffma2(w[8*i+6], u.x, a6);
            a7 = ffma2(w[8*i+7], u.y, a7);
        }
        float2 f0=unpack2(a0), f1=unpack2(a1), f2=unpack2(a2), f3=unpack2(a3);
        float2 f4=unpack2(a4), f5=unpack2(a5), f6=unpack2(a6), f7=unpack2(a7);
        float s = (((f0.x+f0.y)+(f1.x+f1.y)) + ((f2.x+f2.y)+(f3.x+f3.y))) +
                  (((f4.x+f4.y)+(f5.x+f5.y)) + ((f6.x+f6.y)+(f7.x+f7.y)));

        if (!mine) {
            // Publish (partial, tag=t+1) through L2. Single-copy atomic 8B.
            unsigned long long msg;
            asm("mov.b64 %0, {%1, %2};"
                : "=l"(msg)
                : "r"(__float_as_uint(s)), "r"((uint32_t)(t + 1)));
            asm volatile("st.volatile.global.b64 [%0], %1;"
                         :: "l"(send_base + (size_t)buf * 128), "l"(msg)
                         : "memory");
        } else {
            if (t + 1 < T_)
                x_next = __ldg(xpb + (size_t)(t + 1) * H_ + j);
            // Spin on L2 until this step's tag shows up (value rides along).
            const unsigned long long* addr = recv_base + (size_t)buf * 128;
            const uint32_t want = (uint32_t)(t + 1);
            uint32_t lo, hi;
            do {
                asm volatile("ld.volatile.global.v2.u32 {%0, %1}, [%2];"
                             : "=r"(lo), "=r"(hi) : "l"(addr) : "memory");
            } while (hi != want);
            float v = tanh_fast(s + __uint_as_float(lo) + x_cur);
            ysb[(size_t)t * H_ + j] = v;
            if (t + 1 < T_) hs[buf ^ 1u][jl] = v;
            x_cur = x_next;
        }
        __syncthreads();   // h[t+1] visible to senders; local WAR fence
    }
}

// ---------------------------------------------------------------------------
// Launch: gemm0 -> memset -> scan0 -> gemm1 -> memset -> scan1
// ---------------------------------------------------------------------------
extern "C" void kernel_launch(void* const* d_in, const int* in_sizes, int n_in,
                              void* d_out, int out_size)
{
    const float* x     = (const float*)d_in[0];
    const float* W_ih0 = (const float*)d_in[1];
    const float* b_ih0 = (const float*)d_in[2];
    const float* W_hh0 = (const float*)d_in[3];
    const float* W_ih1 = (const float*)d_in[4];
    const float* b_ih1 = (const float*)d_in[5];
    const float* W_hh1 = (const float*)d_in[6];
    float* out = (float*)d_out;

    float *xp, *h;
    unsigned long long* slots;
    cudaGetSymbolAddress((void**)&xp, g_xp);
    cudaGetSymbolAddress((void**)&h,  g_h);
    cudaGetSymbolAddress((void**)&slots, g_slots);
    const size_t slot_bytes = (size_t)B_ * 2 * 2 * 128 * 8;

    dim3 ggrid(M_ / 128, H_ / 64);   // (512, 4)

    gemm_bias<<<ggrid, 256>>>(x, W_ih0, b_ih0, xp);
    cudaMemsetAsync(slots, 0, slot_bytes);
    elman_scan<<<B_ * 2, 256>>>(xp, W_hh0, h, slots);
    gemm_bias<<<ggrid, 256>>>(h, W_ih1, b_ih1, xp);
    cudaMemsetAsync(slots, 0, slot_bytes);
    elman_scan<<<B_ * 2, 256>>>(xp, W_hh1, out, slots);
}